// round 15
// baseline (speedup 1.0000x reference)
#include <cuda_runtime.h>
#include <math.h>
#include <cstdint>

// Fully-fused robotics pipeline (R8 conv/reduce/tail + gmem-direct uniform
// weight loads: no smem weight staging, one fewer __syncthreads).
// 256 threads = 16x16 conv output pixels, each thread computes all 4 output
// channels via packed fma.rn.f32x2 (tap-pairs per channel). Aligned float4
// input loads + shfl_up for the pad-1 column; parallel warp-0 epilogue.
//  inputs: 0 x[1,3,64,64] 1 pose[3] 2 angles[2] 3 ticks[2]
//          4 conv_w[4,3,4,4] 5 conv_b[4] 6 lin_w[2,256] 7 lin_b[2]
//  output: trajectory [19,2] then new_pose [3] -> 41 f32

__device__ __forceinline__ uint64_t pack_f32x2(float lo, float hi) {
    uint64_t r;
    asm("mov.b64 %0, {%1, %2};" : "=l"(r) : "f"(lo), "f"(hi));
    return r;
}
__device__ __forceinline__ void unpack_f32x2(uint64_t v, float& lo, float& hi) {
    asm("mov.b64 {%0, %1}, %2;" : "=f"(lo), "=f"(hi) : "l"(v));
}
__device__ __forceinline__ void ffma_f32x2(uint64_t& d, uint64_t a, uint64_t b) {
    asm("fma.rn.f32x2 %0, %1, %2, %0;" : "+l"(d) : "l"(a), "l"(b));
}

__global__ __launch_bounds__(256, 1)
void robot_fused_kernel(const float* __restrict__ x,
                        const float* __restrict__ pose,
                        const float* __restrict__ angles0,
                        const float* __restrict__ ticks,
                        const float* __restrict__ cw,
                        const float* __restrict__ cb,
                        const float* __restrict__ lw,
                        const float* __restrict__ lb,
                        float* __restrict__ out)
{
    __shared__ float red0[8];
    __shared__ float red1[8];

    const int tid = threadIdx.x;     // 0..255
    const int oh = tid >> 4;         // 0..15 conv output row
    const int ow = tid & 15;         // 0..15 conv output col
    const float4* __restrict__ x4 = (const float4*)x;   // plane = 1024 float4
    const int s = (oh >> 1) * 8 + (ow >> 1);            // pooled flatten idx

    // ---------- FRONT BATCH: every global load, maximum MLP ----------
    // (a) input window: 12 aligned float4 loads (coalesced)
    float4 f[3][4];
#pragma unroll
    for (int ic = 0; ic < 3; ic++) {
#pragma unroll
        for (int kh = 0; kh < 4; kh++) {
            const int ih = oh * 4 - 1 + kh;            // -1..62
            f[ic][kh] = make_float4(0.f, 0.f, 0.f, 0.f);
            if (ih >= 0) f[ic][kh] = x4[ic * 1024 + ih * 16 + ow];
        }
    }
    // (b) conv weights: warp-uniform LDG.128 pairs, kept in registers.
    //     cw[oc][ic][kh][kw] natural order: quad (oc,ic,kh) at cw + oc*48 +
    //     ic*16 + kh*4, 16B aligned -> one ulonglong2 = packed (kw0,kw1),(kw2,kw3).
    ulonglong2 wreg[4][3][4];
    {
        const ulonglong2* cw2 = (const ulonglong2*)cw;  // 48 pairs of f32x2
#pragma unroll
        for (int oc = 0; oc < 4; oc++)
#pragma unroll
            for (int ic = 0; ic < 3; ic++)
#pragma unroll
                for (int kh = 0; kh < 4; kh++)
                    wreg[oc][ic][kh] = cw2[oc * 12 + ic * 4 + kh];
    }
    // (c) linear weights for this pooled index
    float lwa0 = lw[s],             lwa1 = lw[64 + s];
    float lwa2 = lw[128 + s],       lwa3 = lw[192 + s];
    float lwb0 = lw[256 + s],       lwb1 = lw[256 + 64 + s];
    float lwb2 = lw[256 + 128 + s], lwb3 = lw[256 + 192 + s];
    // (d) bias
    const float4 b4 = *(const float4*)cb;
    // (e) tail scalars (lane 0)
    float q1i = 0.f, q2i = 0.f, px0 = 0.f, px1 = 0.f, px2 = 0.f;
    float tk0 = 0.f, tk1 = 0.f, lb0 = 0.f, lb1 = 0.f;
    if (tid == 0) {
        q1i = angles0[0]; q2i = angles0[1];
        px0 = pose[0]; px1 = pose[1]; px2 = pose[2];
        tk0 = ticks[0]; tk1 = ticks[1];
        lb0 = lb[0];   lb1 = lb[1];
    }

    // ---------- conv (packed f32x2) + relu + pool ----------
    // acc[oc] = packed (sum of even taps, sum of odd taps); bias in lo half.
    uint64_t accP0 = pack_f32x2(b4.x, 0.f);
    uint64_t accP1 = pack_f32x2(b4.y, 0.f);
    uint64_t accP2 = pack_f32x2(b4.z, 0.f);
    uint64_t accP3 = pack_f32x2(b4.w, 0.f);

#pragma unroll
    for (int ic = 0; ic < 3; ic++) {
#pragma unroll
        for (int kh = 0; kh < 4; kh++) {
            const float4 v = f[ic][kh];
            // col ow*4-1 lives in the previous lane's .w (pad 0 at ow==0).
            float left = __shfl_up_sync(0xffffffffu, v.w, 1);
            if (ow == 0) left = 0.f;
            const uint64_t xa = pack_f32x2(left, v.x);   // taps kw=0,1
            const uint64_t xb = pack_f32x2(v.y,  v.z);   // taps kw=2,3

            ffma_f32x2(accP0, xa, wreg[0][ic][kh].x);
            ffma_f32x2(accP0, xb, wreg[0][ic][kh].y);
            ffma_f32x2(accP1, xa, wreg[1][ic][kh].x);
            ffma_f32x2(accP1, xb, wreg[1][ic][kh].y);
            ffma_f32x2(accP2, xa, wreg[2][ic][kh].x);
            ffma_f32x2(accP2, xb, wreg[2][ic][kh].y);
            ffma_f32x2(accP3, xa, wreg[3][ic][kh].x);
            ffma_f32x2(accP3, xb, wreg[3][ic][kh].y);
        }
    }

    float lo, hi;
    unpack_f32x2(accP0, lo, hi); float acc0 = lo + hi;
    unpack_f32x2(accP1, lo, hi); float acc1 = lo + hi;
    unpack_f32x2(accP2, lo, hi); float acc2 = lo + hi;
    unpack_f32x2(accP3, lo, hi); float acc3 = lo + hi;

    acc0 = fmaxf(acc0, 0.f); acc1 = fmaxf(acc1, 0.f);
    acc2 = fmaxf(acc2, 0.f); acc3 = fmaxf(acc3, 0.f);

    // 2x2 maxpool: ow pair = lane xor 1, oh pair = lane xor 16 (same warp)
    acc0 = fmaxf(acc0, __shfl_xor_sync(0xffffffffu, acc0, 1));
    acc1 = fmaxf(acc1, __shfl_xor_sync(0xffffffffu, acc1, 1));
    acc2 = fmaxf(acc2, __shfl_xor_sync(0xffffffffu, acc2, 1));
    acc3 = fmaxf(acc3, __shfl_xor_sync(0xffffffffu, acc3, 1));
    acc0 = fmaxf(acc0, __shfl_xor_sync(0xffffffffu, acc0, 16));
    acc1 = fmaxf(acc1, __shfl_xor_sync(0xffffffffu, acc1, 16));
    acc2 = fmaxf(acc2, __shfl_xor_sync(0xffffffffu, acc2, 16));
    acc3 = fmaxf(acc3, __shfl_xor_sync(0xffffffffu, acc3, 16));

    // linear partials (each pooled cell counted 4x; 0.25 compensation below)
    float p0 = acc0 * lwa0 + acc1 * lwa1 + acc2 * lwa2 + acc3 * lwa3;
    float p1 = acc0 * lwb0 + acc1 * lwb1 + acc2 * lwb2 + acc3 * lwb3;

#pragma unroll
    for (int o = 16; o > 0; o >>= 1) {
        p0 += __shfl_down_sync(0xffffffffu, p0, o);
        p1 += __shfl_down_sync(0xffffffffu, p1, o);
    }
    if ((tid & 31) == 0) {
        red0[tid >> 5] = p0;
        red1[tid >> 5] = p1;
    }
    __syncthreads();

    // ---------- tail on warp 0 ----------
    if (tid < 32) {
        float sx, sy;                 // arm start position (broadcast later)
        if (tid == 0) {
            float t0 = 0.f, t1 = 0.f;
#pragma unroll
            for (int i = 0; i < 8; i++) { t0 += red0[i]; t1 += red1[i]; }
            const float tx = lb0 + 0.25f * t0;
            const float ty = lb1 + 0.25f * t1;

            // IK: 9 Newton steps, MUFU trig + fast division
            float q1 = q1i, q2 = q2i;
#pragma unroll
            for (int st = 0; st < 9; st++) {
                float s1  = __sinf(q1),      c1  = __cosf(q1);
                float s12 = __sinf(q1 + q2), c12 = __cosf(q1 + q2);
                float ex = tx - (c1 + c12), ey = ty - (s1 + s12);
                float j11 = -s1 - s12, j12 = -s12;
                float j21 =  c1 + c12, j22 =  c12;
                float det = j11 * j22 - j12 * j21;
                float inv = __fdividef(1.0f, det + 1e-6f);
                q1 += (j22 * ex - j12 * ey) * inv;   // ALPHA = 1
                q2 += (-j21 * ex + j11 * ey) * inv;
            }
            sx = __cosf(q1) + __cosf(q1 + q2);
            sy = __sinf(q1) + __sinf(q1 + q2);

            // odometry (cheap, serial on lane 0)
            float dl = tk0 * 1e-4f;
            float dr = tk1 * 1e-4f;
            float dc = 0.5f * (dl + dr);
            float dth = (dr - dl) * 2.0f;      // / AXLE_WIDTH(0.5)
            float avg = px2 + 0.5f * dth;
            float2 o0 = make_float2(px0 + dc * __cosf(avg),
                                    px1 + dc * __sinf(avg));
            *(float2*)&out[38] = o0;
            out[40] = px2 + dth;
        }
        // broadcast start position to all lanes of warp 0
        sx = __shfl_sync(0xffffffffu, sx, 0);
        sy = __shfl_sync(0xffffffffu, sy, 0);

        // trajectory: start -> mid(-0.2,0) -> end(0,-0.1), 19 points.
        // lane k (0..18) writes point k as one float2 store.
        if (tid < 19) {
            const float mx0 = sx - 0.2f, my0 = sy;
            float vx, vy;
            if (tid < 10) {
                float t = (float)tid * (1.0f / 9.0f);
                vx = sx * (1.0f - t) + mx0 * t;
                vy = sy * (1.0f - t) + my0 * t;  // == sy
            } else {
                int k = tid - 9;                 // 1..9
                float t = (float)k * (1.0f / 9.0f);
                vx = mx0;                        // seg2: x constant at mid
                vy = my0 - 0.1f * t;             // my0*(1-t) + (my0-0.1)*t
            }
            *(float2*)&out[2 * tid] = make_float2(vx, vy);
        }
    }
}

extern "C" void kernel_launch(void* const* d_in, const int* in_sizes, int n_in,
                              void* d_out, int out_size)
{
    const float* x       = (const float*)d_in[0];
    const float* pose    = (const float*)d_in[1];
    const float* angles0 = (const float*)d_in[2];
    const float* ticks   = (const float*)d_in[3];
    const float* cw      = (const float*)d_in[4];
    const float* cb      = (const float*)d_in[5];
    const float* lw      = (const float*)d_in[6];
    const float* lb      = (const float*)d_in[7];
    float* out = (float*)d_out;

    robot_fused_kernel<<<1, 256>>>(x, pose, angles0, ticks, cw, cb, lw, lb, out);
}

// round 16
// speedup vs baseline: 1.0339x; 1.0339x over previous
#include <cuda_runtime.h>
#include <math.h>
#include <cstdint>

// FINAL: fully-fused robotics pipeline (R8 configuration; best verified
// 6.62/6.66/6.88us over three runs, rel_err 1.05e-6; all structural
// variants R9/R11/R13 regressed).
// 256 threads = 16x16 conv output pixels, each thread computes all 4 output
// channels via packed fma.rn.f32x2 (tap-pairs per channel). Aligned float4
// input loads + shfl_up for the pad-1 column; smem-staged transant weights;
// 5-level reduce with 0.25 compensation; parallel warp-0 trajectory epilogue.
//  inputs: 0 x[1,3,64,64] 1 pose[3] 2 angles[2] 3 ticks[2]
//          4 conv_w[4,3,4,4] 5 conv_b[4] 6 lin_w[2,256] 7 lin_b[2]
//  output: trajectory [19,2] then new_pose [3] -> 41 f32

__device__ __forceinline__ uint64_t pack_f32x2(float lo, float hi) {
    uint64_t r;
    asm("mov.b64 %0, {%1, %2};" : "=l"(r) : "f"(lo), "f"(hi));
    return r;
}
__device__ __forceinline__ void unpack_f32x2(uint64_t v, float& lo, float& hi) {
    asm("mov.b64 {%0, %1}, %2;" : "=f"(lo), "=f"(hi) : "l"(v));
}
__device__ __forceinline__ void ffma_f32x2(uint64_t& d, uint64_t a, uint64_t b) {
    asm("fma.rn.f32x2 %0, %1, %2, %0;" : "+l"(d) : "l"(a), "l"(b));
}

__global__ __launch_bounds__(256, 1)
void robot_fused_kernel(const float* __restrict__ x,
                        const float* __restrict__ pose,
                        const float* __restrict__ angles0,
                        const float* __restrict__ ticks,
                        const float* __restrict__ cw,
                        const float* __restrict__ cb,
                        const float* __restrict__ lw,
                        const float* __restrict__ lb,
                        float* __restrict__ out)
{
    __shared__ __align__(16) float ws[192];  // conv weights, NATURAL order
    __shared__ float red0[8];
    __shared__ float red1[8];

    const int tid = threadIdx.x;     // 0..255
    const int oh = tid >> 4;         // 0..15 conv output row
    const int ow = tid & 15;         // 0..15 conv output col
    const float4* __restrict__ x4 = (const float4*)x;   // plane = 1024 float4
    const int s = (oh >> 1) * 8 + (ow >> 1);            // pooled flatten idx

    // ---------- FRONT BATCH: every global load, maximum MLP ----------
    float4 f[3][4];
#pragma unroll
    for (int ic = 0; ic < 3; ic++) {
#pragma unroll
        for (int kh = 0; kh < 4; kh++) {
            const int ih = oh * 4 - 1 + kh;            // -1..62
            f[ic][kh] = make_float4(0.f, 0.f, 0.f, 0.f);
            if (ih >= 0) f[ic][kh] = x4[ic * 1024 + ih * 16 + ow];
        }
    }
    float lwa0 = lw[s],             lwa1 = lw[64 + s];
    float lwa2 = lw[128 + s],       lwa3 = lw[192 + s];
    float lwb0 = lw[256 + s],       lwb1 = lw[256 + 64 + s];
    float lwb2 = lw[256 + 128 + s], lwb3 = lw[256 + 192 + s];
    const float4 b4 = *(const float4*)cb;
    float wstage = 0.f;
    if (tid < 192) wstage = cw[tid];
    float q1i = 0.f, q2i = 0.f, px0 = 0.f, px1 = 0.f, px2 = 0.f;
    float tk0 = 0.f, tk1 = 0.f, lb0 = 0.f, lb1 = 0.f;
    if (tid == 0) {
        q1i = angles0[0]; q2i = angles0[1];
        px0 = pose[0]; px1 = pose[1]; px2 = pose[2];
        tk0 = ticks[0]; tk1 = ticks[1];
        lb0 = lb[0];   lb1 = lb[1];
    }

    // Stage conv weights in natural cw[oc][ic][kh][kw] order
    if (tid < 192) ws[tid] = wstage;
    __syncthreads();

    // ---------- conv (packed f32x2) + relu + pool ----------
    // acc[oc] = packed (sum of even taps, sum of odd taps); bias in lo half.
    uint64_t accP0 = pack_f32x2(b4.x, 0.f);
    uint64_t accP1 = pack_f32x2(b4.y, 0.f);
    uint64_t accP2 = pack_f32x2(b4.z, 0.f);
    uint64_t accP3 = pack_f32x2(b4.w, 0.f);

#pragma unroll
    for (int ic = 0; ic < 3; ic++) {
#pragma unroll
        for (int kh = 0; kh < 4; kh++) {
            const float4 v = f[ic][kh];
            // col ow*4-1 lives in the previous lane's .w (pad 0 at ow==0).
            float left = __shfl_up_sync(0xffffffffu, v.w, 1);
            if (ow == 0) left = 0.f;
            const uint64_t xa = pack_f32x2(left, v.x);   // taps kw=0,1
            const uint64_t xb = pack_f32x2(v.y,  v.z);   // taps kw=2,3

            const int base = ic * 16 + kh * 4;           // + oc*48
            const ulonglong2 w0 = *(const ulonglong2*)&ws[base];
            const ulonglong2 w1 = *(const ulonglong2*)&ws[base + 48];
            const ulonglong2 w2 = *(const ulonglong2*)&ws[base + 96];
            const ulonglong2 w3 = *(const ulonglong2*)&ws[base + 144];
            ffma_f32x2(accP0, xa, w0.x); ffma_f32x2(accP0, xb, w0.y);
            ffma_f32x2(accP1, xa, w1.x); ffma_f32x2(accP1, xb, w1.y);
            ffma_f32x2(accP2, xa, w2.x); ffma_f32x2(accP2, xb, w2.y);
            ffma_f32x2(accP3, xa, w3.x); ffma_f32x2(accP3, xb, w3.y);
        }
    }

    float lo, hi;
    unpack_f32x2(accP0, lo, hi); float acc0 = lo + hi;
    unpack_f32x2(accP1, lo, hi); float acc1 = lo + hi;
    unpack_f32x2(accP2, lo, hi); float acc2 = lo + hi;
    unpack_f32x2(accP3, lo, hi); float acc3 = lo + hi;

    acc0 = fmaxf(acc0, 0.f); acc1 = fmaxf(acc1, 0.f);
    acc2 = fmaxf(acc2, 0.f); acc3 = fmaxf(acc3, 0.f);

    // 2x2 maxpool: ow pair = lane xor 1, oh pair = lane xor 16 (same warp)
    acc0 = fmaxf(acc0, __shfl_xor_sync(0xffffffffu, acc0, 1));
    acc1 = fmaxf(acc1, __shfl_xor_sync(0xffffffffu, acc1, 1));
    acc2 = fmaxf(acc2, __shfl_xor_sync(0xffffffffu, acc2, 1));
    acc3 = fmaxf(acc3, __shfl_xor_sync(0xffffffffu, acc3, 1));
    acc0 = fmaxf(acc0, __shfl_xor_sync(0xffffffffu, acc0, 16));
    acc1 = fmaxf(acc1, __shfl_xor_sync(0xffffffffu, acc1, 16));
    acc2 = fmaxf(acc2, __shfl_xor_sync(0xffffffffu, acc2, 16));
    acc3 = fmaxf(acc3, __shfl_xor_sync(0xffffffffu, acc3, 16));

    // linear partials (each pooled cell counted 4x; 0.25 compensation below)
    float p0 = acc0 * lwa0 + acc1 * lwa1 + acc2 * lwa2 + acc3 * lwa3;
    float p1 = acc0 * lwb0 + acc1 * lwb1 + acc2 * lwb2 + acc3 * lwb3;

#pragma unroll
    for (int o = 16; o > 0; o >>= 1) {
        p0 += __shfl_down_sync(0xffffffffu, p0, o);
        p1 += __shfl_down_sync(0xffffffffu, p1, o);
    }
    if ((tid & 31) == 0) {
        red0[tid >> 5] = p0;
        red1[tid >> 5] = p1;
    }
    __syncthreads();

    // ---------- tail on warp 0 ----------
    if (tid < 32) {
        float sx, sy;                 // arm start position (broadcast later)
        if (tid == 0) {
            float t0 = 0.f, t1 = 0.f;
#pragma unroll
            for (int i = 0; i < 8; i++) { t0 += red0[i]; t1 += red1[i]; }
            const float tx = lb0 + 0.25f * t0;
            const float ty = lb1 + 0.25f * t1;

            // IK: 9 Newton steps, MUFU trig + fast division
            float q1 = q1i, q2 = q2i;
#pragma unroll
            for (int st = 0; st < 9; st++) {
                float s1  = __sinf(q1),      c1  = __cosf(q1);
                float s12 = __sinf(q1 + q2), c12 = __cosf(q1 + q2);
                float ex = tx - (c1 + c12), ey = ty - (s1 + s12);
                float j11 = -s1 - s12, j12 = -s12;
                float j21 =  c1 + c12, j22 =  c12;
                float det = j11 * j22 - j12 * j21;
                float inv = __fdividef(1.0f, det + 1e-6f);
                q1 += (j22 * ex - j12 * ey) * inv;   // ALPHA = 1
                q2 += (-j21 * ex + j11 * ey) * inv;
            }
            sx = __cosf(q1) + __cosf(q1 + q2);
            sy = __sinf(q1) + __sinf(q1 + q2);

            // odometry (cheap, serial on lane 0)
            float dl = tk0 * 1e-4f;
            float dr = tk1 * 1e-4f;
            float dc = 0.5f * (dl + dr);
            float dth = (dr - dl) * 2.0f;      // / AXLE_WIDTH(0.5)
            float avg = px2 + 0.5f * dth;
            float2 o0 = make_float2(px0 + dc * __cosf(avg),
                                    px1 + dc * __sinf(avg));
            *(float2*)&out[38] = o0;
            out[40] = px2 + dth;
        }
        // broadcast start position to all lanes of warp 0
        sx = __shfl_sync(0xffffffffu, sx, 0);
        sy = __shfl_sync(0xffffffffu, sy, 0);

        // trajectory: start -> mid(-0.2,0) -> end(0,-0.1), 19 points.
        // lane k (0..18) writes point k as one float2 store.
        if (tid < 19) {
            const float mx0 = sx - 0.2f, my0 = sy;
            float vx, vy;
            if (tid < 10) {
                float t = (float)tid * (1.0f / 9.0f);
                vx = sx * (1.0f - t) + mx0 * t;
                vy = sy * (1.0f - t) + my0 * t;  // == sy
            } else {
                int k = tid - 9;                 // 1..9
                float t = (float)k * (1.0f / 9.0f);
                vx = mx0;                        // seg2: x constant at mid
                vy = my0 - 0.1f * t;             // my0*(1-t) + (my0-0.1)*t
            }
            *(float2*)&out[2 * tid] = make_float2(vx, vy);
        }
    }
}

extern "C" void kernel_launch(void* const* d_in, const int* in_sizes, int n_in,
                              void* d_out, int out_size)
{
    const float* x       = (const float*)d_in[0];
    const float* pose    = (const float*)d_in[1];
    const float* angles0 = (const float*)d_in[2];
    const float* ticks   = (const float*)d_in[3];
    const float* cw      = (const float*)d_in[4];
    const float* cb      = (const float*)d_in[5];
    const float* lw      = (const float*)d_in[6];
    const float* lb      = (const float*)d_in[7];
    float* out = (float*)d_out;

    robot_fused_kernel<<<1, 256>>>(x, pose, angles0, ticks, cw, cb, lw, lb, out);
}

// round 17
// speedup vs baseline: 1.1787x; 1.1401x over previous
#include <cuda_runtime.h>
#include <math.h>
#include <cstdint>

// FINAL: fully-fused robotics pipeline (R8 configuration; best verified
// 6.62us; same-binary scatter 6.6-7.6us is clock-state noise, not code).
// 256 threads = 16x16 conv output pixels, each thread computes all 4 output
// channels via packed fma.rn.f32x2 (tap-pairs per channel). Aligned float4
// input loads + shfl_up for the pad-1 column; smem-staged weights; 5-level
// reduce with 0.25 compensation; parallel warp-0 trajectory epilogue.
//  inputs: 0 x[1,3,64,64] 1 pose[3] 2 angles[2] 3 ticks[2]
//          4 conv_w[4,3,4,4] 5 conv_b[4] 6 lin_w[2,256] 7 lin_b[2]
//  output: trajectory [19,2] then new_pose [3] -> 41 f32

__device__ __forceinline__ uint64_t pack_f32x2(float lo, float hi) {
    uint64_t r;
    asm("mov.b64 %0, {%1, %2};" : "=l"(r) : "f"(lo), "f"(hi));
    return r;
}
__device__ __forceinline__ void unpack_f32x2(uint64_t v, float& lo, float& hi) {
    asm("mov.b64 {%0, %1}, %2;" : "=f"(lo), "=f"(hi) : "l"(v));
}
__device__ __forceinline__ void ffma_f32x2(uint64_t& d, uint64_t a, uint64_t b) {
    asm("fma.rn.f32x2 %0, %1, %2, %0;" : "+l"(d) : "l"(a), "l"(b));
}

__global__ __launch_bounds__(256, 1)
void robot_fused_kernel(const float* __restrict__ x,
                        const float* __restrict__ pose,
                        const float* __restrict__ angles0,
                        const float* __restrict__ ticks,
                        const float* __restrict__ cw,
                        const float* __restrict__ cb,
                        const float* __restrict__ lw,
                        const float* __restrict__ lb,
                        float* __restrict__ out)
{
    __shared__ __align__(16) float ws[192];  // conv weights, NATURAL order
    __shared__ float red0[8];
    __shared__ float red1[8];

    const int tid = threadIdx.x;     // 0..255
    const int oh = tid >> 4;         // 0..15 conv output row
    const int ow = tid & 15;         // 0..15 conv output col
    const float4* __restrict__ x4 = (const float4*)x;   // plane = 1024 float4
    const int s = (oh >> 1) * 8 + (ow >> 1);            // pooled flatten idx

    // ---------- FRONT BATCH: every global load, maximum MLP ----------
    float4 f[3][4];
#pragma unroll
    for (int ic = 0; ic < 3; ic++) {
#pragma unroll
        for (int kh = 0; kh < 4; kh++) {
            const int ih = oh * 4 - 1 + kh;            // -1..62
            f[ic][kh] = make_float4(0.f, 0.f, 0.f, 0.f);
            if (ih >= 0) f[ic][kh] = x4[ic * 1024 + ih * 16 + ow];
        }
    }
    float lwa0 = lw[s],             lwa1 = lw[64 + s];
    float lwa2 = lw[128 + s],       lwa3 = lw[192 + s];
    float lwb0 = lw[256 + s],       lwb1 = lw[256 + 64 + s];
    float lwb2 = lw[256 + 128 + s], lwb3 = lw[256 + 192 + s];
    const float4 b4 = *(const float4*)cb;
    float wstage = 0.f;
    if (tid < 192) wstage = cw[tid];
    float q1i = 0.f, q2i = 0.f, px0 = 0.f, px1 = 0.f, px2 = 0.f;
    float tk0 = 0.f, tk1 = 0.f, lb0 = 0.f, lb1 = 0.f;
    if (tid == 0) {
        q1i = angles0[0]; q2i = angles0[1];
        px0 = pose[0]; px1 = pose[1]; px2 = pose[2];
        tk0 = ticks[0]; tk1 = ticks[1];
        lb0 = lb[0];   lb1 = lb[1];
    }

    // Stage conv weights in natural cw[oc][ic][kh][kw] order
    if (tid < 192) ws[tid] = wstage;
    __syncthreads();

    // ---------- conv (packed f32x2) + relu + pool ----------
    // acc[oc] = packed (sum of even taps, sum of odd taps); bias in lo half.
    uint64_t accP0 = pack_f32x2(b4.x, 0.f);
    uint64_t accP1 = pack_f32x2(b4.y, 0.f);
    uint64_t accP2 = pack_f32x2(b4.z, 0.f);
    uint64_t accP3 = pack_f32x2(b4.w, 0.f);

#pragma unroll
    for (int ic = 0; ic < 3; ic++) {
#pragma unroll
        for (int kh = 0; kh < 4; kh++) {
            const float4 v = f[ic][kh];
            // col ow*4-1 lives in the previous lane's .w (pad 0 at ow==0).
            float left = __shfl_up_sync(0xffffffffu, v.w, 1);
            if (ow == 0) left = 0.f;
            const uint64_t xa = pack_f32x2(left, v.x);   // taps kw=0,1
            const uint64_t xb = pack_f32x2(v.y,  v.z);   // taps kw=2,3

            const int base = ic * 16 + kh * 4;           // + oc*48
            const ulonglong2 w0 = *(const ulonglong2*)&ws[base];
            const ulonglong2 w1 = *(const ulonglong2*)&ws[base + 48];
            const ulonglong2 w2 = *(const ulonglong2*)&ws[base + 96];
            const ulonglong2 w3 = *(const ulonglong2*)&ws[base + 144];
            ffma_f32x2(accP0, xa, w0.x); ffma_f32x2(accP0, xb, w0.y);
            ffma_f32x2(accP1, xa, w1.x); ffma_f32x2(accP1, xb, w1.y);
            ffma_f32x2(accP2, xa, w2.x); ffma_f32x2(accP2, xb, w2.y);
            ffma_f32x2(accP3, xa, w3.x); ffma_f32x2(accP3, xb, w3.y);
        }
    }

    float lo, hi;
    unpack_f32x2(accP0, lo, hi); float acc0 = lo + hi;
    unpack_f32x2(accP1, lo, hi); float acc1 = lo + hi;
    unpack_f32x2(accP2, lo, hi); float acc2 = lo + hi;
    unpack_f32x2(accP3, lo, hi); float acc3 = lo + hi;

    acc0 = fmaxf(acc0, 0.f); acc1 = fmaxf(acc1, 0.f);
    acc2 = fmaxf(acc2, 0.f); acc3 = fmaxf(acc3, 0.f);

    // 2x2 maxpool: ow pair = lane xor 1, oh pair = lane xor 16 (same warp)
    acc0 = fmaxf(acc0, __shfl_xor_sync(0xffffffffu, acc0, 1));
    acc1 = fmaxf(acc1, __shfl_xor_sync(0xffffffffu, acc1, 1));
    acc2 = fmaxf(acc2, __shfl_xor_sync(0xffffffffu, acc2, 1));
    acc3 = fmaxf(acc3, __shfl_xor_sync(0xffffffffu, acc3, 1));
    acc0 = fmaxf(acc0, __shfl_xor_sync(0xffffffffu, acc0, 16));
    acc1 = fmaxf(acc1, __shfl_xor_sync(0xffffffffu, acc1, 16));
    acc2 = fmaxf(acc2, __shfl_xor_sync(0xffffffffu, acc2, 16));
    acc3 = fmaxf(acc3, __shfl_xor_sync(0xffffffffu, acc3, 16));

    // linear partials (each pooled cell counted 4x; 0.25 compensation below)
    float p0 = acc0 * lwa0 + acc1 * lwa1 + acc2 * lwa2 + acc3 * lwa3;
    float p1 = acc0 * lwb0 + acc1 * lwb1 + acc2 * lwb2 + acc3 * lwb3;

#pragma unroll
    for (int o = 16; o > 0; o >>= 1) {
        p0 += __shfl_down_sync(0xffffffffu, p0, o);
        p1 += __shfl_down_sync(0xffffffffu, p1, o);
    }
    if ((tid & 31) == 0) {
        red0[tid >> 5] = p0;
        red1[tid >> 5] = p1;
    }
    __syncthreads();

    // ---------- tail on warp 0 ----------
    if (tid < 32) {
        float sx, sy;                 // arm start position (broadcast later)
        if (tid == 0) {
            float t0 = 0.f, t1 = 0.f;
#pragma unroll
            for (int i = 0; i < 8; i++) { t0 += red0[i]; t1 += red1[i]; }
            const float tx = lb0 + 0.25f * t0;
            const float ty = lb1 + 0.25f * t1;

            // IK: 9 Newton steps, MUFU trig + fast division
            float q1 = q1i, q2 = q2i;
#pragma unroll
            for (int st = 0; st < 9; st++) {
                float s1  = __sinf(q1),      c1  = __cosf(q1);
                float s12 = __sinf(q1 + q2), c12 = __cosf(q1 + q2);
                float ex = tx - (c1 + c12), ey = ty - (s1 + s12);
                float j11 = -s1 - s12, j12 = -s12;
                float j21 =  c1 + c12, j22 =  c12;
                float det = j11 * j22 - j12 * j21;
                float inv = __fdividef(1.0f, det + 1e-6f);
                q1 += (j22 * ex - j12 * ey) * inv;   // ALPHA = 1
                q2 += (-j21 * ex + j11 * ey) * inv;
            }
            sx = __cosf(q1) + __cosf(q1 + q2);
            sy = __sinf(q1) + __sinf(q1 + q2);

            // odometry (cheap, serial on lane 0)
            float dl = tk0 * 1e-4f;
            float dr = tk1 * 1e-4f;
            float dc = 0.5f * (dl + dr);
            float dth = (dr - dl) * 2.0f;      // / AXLE_WIDTH(0.5)
            float avg = px2 + 0.5f * dth;
            float2 o0 = make_float2(px0 + dc * __cosf(avg),
                                    px1 + dc * __sinf(avg));
            *(float2*)&out[38] = o0;
            out[40] = px2 + dth;
        }
        // broadcast start position to all lanes of warp 0
        sx = __shfl_sync(0xffffffffu, sx, 0);
        sy = __shfl_sync(0xffffffffu, sy, 0);

        // trajectory: start -> mid(-0.2,0) -> end(0,-0.1), 19 points.
        // lane k (0..18) writes point k as one float2 store.
        if (tid < 19) {
            const float mx0 = sx - 0.2f, my0 = sy;
            float vx, vy;
            if (tid < 10) {
                float t = (float)tid * (1.0f / 9.0f);
                vx = sx * (1.0f - t) + mx0 * t;
                vy = sy * (1.0f - t) + my0 * t;  // == sy
            } else {
                int k = tid - 9;                 // 1..9
                float t = (float)k * (1.0f / 9.0f);
                vx = mx0;                        // seg2: x constant at mid
                vy = my0 - 0.1f * t;             // my0*(1-t) + (my0-0.1)*t
            }
            *(float2*)&out[2 * tid] = make_float2(vx, vy);
        }
    }
}

extern "C" void kernel_launch(void* const* d_in, const int* in_sizes, int n_in,
                              void* d_out, int out_size)
{
    const float* x       = (const float*)d_in[0];
    const float* pose    = (const float*)d_in[1];
    const float* angles0 = (const float*)d_in[2];
    const float* ticks   = (const float*)d_in[3];
    const float* cw      = (const float*)d_in[4];
    const float* cb      = (const float*)d_in[5];
    const float* lw      = (const float*)d_in[6];
    const float* lb      = (const float*)d_in[7];
    float* out = (float*)d_out;

    robot_fused_kernel<<<1, 256>>>(x, pose, angles0, ticks, cw, cb, lw, lb, out);
}